// round 16
// baseline (speedup 1.0000x reference)
#include <cuda_runtime.h>
#include <cuda_bf16.h>
#include <math.h>
#include <stdint.h>

#define NN 100000
#define NE 400000
#define HIDN 128
#define HDD 256

// -------- device scratch (allocation-free rule: __device__ globals) --------
__device__ float g_q[NN * HDD];
__device__ float g_k[NN * HDD];
__device__ float g_v[NN * HDD];
__device__ float g_o[NN * HDD];          // skip output (input to attn)
__device__ float g_PQ[NN * HDD];         // [P | Q] per node (256)
__device__ __nv_bfloat16 g_ahi[NN * HIDN];
__device__ __nv_bfloat16 g_alo[NN * HIDN];
__device__ __nv_bfloat16 g_ohi[NN * HDD];
__device__ __nv_bfloat16 g_olo[NN * HDD];
// WT layout: node weight w at w*32768 ([256 n,128 k]); pq at 131072 ([256 n,256 k])
#define WT_PQ_OFS 131072
__device__ __nv_bfloat16 g_wthi[196608];
__device__ __nv_bfloat16 g_wtlo[196608];
// W2^T [64 n][128 k] hi/lo
__device__ __nv_bfloat16 g_w2h[8192];
__device__ __nv_bfloat16 g_w2l[8192];
__device__ int g_src[NE];
__device__ int g_dst[NE];
__device__ int g_cnt[NN];
__device__ int g_off[NN + 1];
__device__ int g_eid[NE];                // CSR-ordered SRC node ids

// ---------------------------- helpers --------------------------------------
__device__ __forceinline__ uint32_t smem_u32(const void* p) {
    uint32_t a;
    asm("{ .reg .u64 t; cvta.to.shared.u64 t, %1; cvt.u32.u64 %0, t; }"
        : "=r"(a) : "l"(p));
    return a;
}
__device__ __forceinline__ void ldsm4(uint32_t addr, uint32_t r[4]) {
    asm volatile("ldmatrix.sync.aligned.m8n8.x4.shared.b16 {%0,%1,%2,%3}, [%4];"
                 : "=r"(r[0]), "=r"(r[1]), "=r"(r[2]), "=r"(r[3]) : "r"(addr));
}
__device__ __forceinline__ void mma16816(float d[4], const uint32_t a[4],
                                         const uint32_t b[2]) {
    asm volatile(
        "mma.sync.aligned.m16n8k16.row.col.f32.bf16.bf16.f32 "
        "{%0,%1,%2,%3},{%4,%5,%6,%7},{%8,%9},{%0,%1,%2,%3};"
        : "+f"(d[0]), "+f"(d[1]), "+f"(d[2]), "+f"(d[3])
        : "r"(a[0]), "r"(a[1]), "r"(a[2]), "r"(a[3]), "r"(b[0]), "r"(b[1]));
}
__device__ __forceinline__ void cp16(uint32_t dst, const void* src, uint32_t nbytes) {
    asm volatile("cp.async.cg.shared.global [%0], [%1], 16, %2;"
                 :: "r"(dst), "l"(src), "r"(nbytes) : "memory");
}
#define CP_COMMIT() asm volatile("cp.async.commit_group;" ::: "memory")
#define CP_WAIT0()  asm volatile("cp.async.wait_group 0;" ::: "memory")
#define CP_WAIT1()  asm volatile("cp.async.wait_group 1;" ::: "memory")

// ---------------------------- CSR build ------------------------------------
__global__ void __launch_bounds__(256) zero_cnt() {
    int i = blockIdx.x * 256 + threadIdx.x;
    if (i < NN) g_cnt[i] = 0;
}
__global__ void __launch_bounds__(256) prep_kernel(const int* __restrict__ ei) {
    int i = blockIdx.x * 256 + threadIdx.x;
    if (i < NE) {
        int s = ei[i];
        int d = ei[NE + i];
        s = s < 0 ? 0 : (s >= NN ? NN - 1 : s);
        d = d < 0 ? 0 : (d >= NN ? NN - 1 : d);
        g_src[i] = s;
        g_dst[i] = d;
        atomicAdd(&g_cnt[d], 1);
    }
}
#define SCAN_T 1024
__global__ void __launch_bounds__(SCAN_T) scan_kernel() {
    __shared__ int tot[SCAN_T];
    int t = threadIdx.x;
    const int CH = (NN + SCAN_T - 1) / SCAN_T;
    int b = t * CH, e = b + CH < NN ? b + CH : NN;
    int s = 0;
    for (int i = b; i < e; i++) s += g_cnt[i];
    tot[t] = s;
    __syncthreads();
    #pragma unroll
    for (int d = 1; d < SCAN_T; d <<= 1) {
        int v = t >= d ? tot[t - d] : 0;
        __syncthreads();
        tot[t] += v;
        __syncthreads();
    }
    int running = t > 0 ? tot[t - 1] : 0;
    for (int i = b; i < e; i++) {
        int c = g_cnt[i];
        g_off[i] = running;
        g_cnt[i] = running;
        running += c;
    }
    if (t == SCAN_T - 1) g_off[NN] = NE;
}
// store SRC directly in CSR order (kills one indirection in attn)
__global__ void __launch_bounds__(256) scatter_kernel() {
    int i = blockIdx.x * 256 + threadIdx.x;
    if (i < NE) {
        int pos = atomicAdd(&g_cnt[g_dst[i]], 1);
        g_eid[pos] = g_src[i];
    }
}

// ---------------------------- conversions ----------------------------------
__device__ __forceinline__ void split_bf(float a, __nv_bfloat16& h, __nv_bfloat16& l) {
    h = __float2bfloat16(a);
    l = __float2bfloat16(a - __bfloat162float(h));
}

__global__ void __launch_bounds__(256) conv_h(const float* __restrict__ x,
                                              const float* __restrict__ mem) {
    int i4 = blockIdx.x * 256 + threadIdx.x;
    if (i4 >= NN * HIDN / 4) return;
    float4 xv = *(const float4*)(x + i4 * 4);
    float4 mv = *(const float4*)(mem + i4 * 4);
    float a[4] = {xv.x + mv.x, xv.y + mv.y, xv.z + mv.z, xv.w + mv.w};
    __nv_bfloat16 h[4], l[4];
    #pragma unroll
    for (int j = 0; j < 4; j++) split_bf(a[j], h[j], l[j]);
    *(uint2*)(g_ahi + i4 * 4) = *(uint2*)h;
    *(uint2*)(g_alo + i4 * 4) = *(uint2*)l;
}

// WT[n][k] = W[k][n]; also W2T [64][128]
#define CW_TOT 204800
__global__ void __launch_bounds__(256) conv_w(
    const float* __restrict__ Wq, const float* __restrict__ Wk,
    const float* __restrict__ Wv, const float* __restrict__ Ws,
    const float* __restrict__ W1, const float* __restrict__ W2)
{
    int e = blockIdx.x * 256 + threadIdx.x;
    if (e >= CW_TOT) return;
    float a;
    if (e < WT_PQ_OFS) {
        int w = e >> 15, r = e & 32767;
        int n = r >> 7, k = r & 127;
        const float* W = (w == 0) ? Wq : (w == 1) ? Wk : (w == 2) ? Wv : Ws;
        a = W[k * 256 + n];
    } else if (e < 196608) {
        int f = e - WT_PQ_OFS;
        int n = f >> 8, k = f & 255;
        a = (n < 128) ? W1[k * 128 + n] : W1[(256 + k) * 128 + (n - 128)];
    } else {
        int f = e - 196608;
        int n = f >> 7, k = f & 127;
        a = W2[k * 64 + n];
        __nv_bfloat16 h, l;
        split_bf(a, h, l);
        g_w2h[f] = h;
        g_w2l[f] = l;
        return;
    }
    __nv_bfloat16 h, l;
    split_bf(a, h, l);
    g_wthi[e] = h;
    g_wtlo[e] = l;
}

#define TSTRIDE 136

// ---------------------------------------------------------------------------
// gemm_node2: M=128 block tile; A (hi/lo) loaded ONCE; loop over all 8
// (weight, col-half) B tiles with double-buffered cp.async.
// smem: A 2x34816 + B 2 bufs x 2x34816 = 208896 B (1 block/SM).
// 8 warps: 4m x 2n, 32x64 warp tiles.
// ---------------------------------------------------------------------------
#define N2_A_HI 0
#define N2_A_LO 34816
#define N2_B(buf) (69632 + (buf) * 69632)      // hi at +0, lo at +34816
#define N2_SMEM 208896

__global__ void __launch_bounds__(256) gemm_node2(
    const __nv_bfloat16* __restrict__ ahi, const __nv_bfloat16* __restrict__ alo,
    const __nv_bfloat16* __restrict__ wthi, const __nv_bfloat16* __restrict__ wtlo,
    const float* __restrict__ bq, const float* __restrict__ bk,
    const float* __restrict__ bv, const float* __restrict__ bs,
    float* __restrict__ oq, float* __restrict__ ok,
    float* __restrict__ ov, float* __restrict__ og)
{
    extern __shared__ __nv_bfloat16 smem[];
    int t = threadIdx.x, lane = t & 31, wid = t >> 5;
    int bm = blockIdx.x * 128;
    uint32_t base = smem_u32(smem);

    // A tiles (128x128 hi+lo), zero-fill rows >= NN
    #pragma unroll
    for (int it = 0; it < 8; it++) {
        int idx = t + it * 256;
        int row = idx >> 4, c16 = idx & 15;
        int grow = bm + row;
        uint32_t nb = grow < NN ? 16u : 0u;
        uint32_t doff = (uint32_t)((row * TSTRIDE + c16 * 8) * 2);
        cp16(base + N2_A_HI + doff, ahi + (size_t)grow * HIDN + c16 * 8, nb);
        cp16(base + N2_A_LO + doff, alo + (size_t)grow * HIDN + c16 * 8, nb);
    }
    // B tile 0
    #pragma unroll
    for (int it = 0; it < 8; it++) {
        int idx = t + it * 256;
        int row = idx >> 4, c16 = idx & 15;
        uint32_t doff = (uint32_t)((row * TSTRIDE + c16 * 8) * 2);
        cp16(base + N2_B(0) + doff, wthi + row * 128 + c16 * 8, 16u);
        cp16(base + N2_B(0) + 34816 + doff, wtlo + row * 128 + c16 * 8, 16u);
    }
    CP_COMMIT();

    int wm = (wid & 3) * 32;
    int wn = (wid >> 2) * 64;
    int aRow = wm + ((lane >> 3) & 1) * 8 + (lane & 7);
    int aK0 = (lane >> 4) * 8;
    int bRow = wn + (lane >> 4) * 8 + (lane & 7);
    int bK0 = ((lane >> 3) & 1) * 8;

    for (int itw = 0; itw < 8; itw++) {
        if (itw < 7) {
            const __nv_bfloat16* bh = wthi + (size_t)(itw + 1) * 16384;
            const __nv_bfloat16* bl = wtlo + (size_t)(itw + 1) * 16384;
            uint32_t bb = base + N2_B((itw + 1) & 1);
            #pragma unroll
            for (int it = 0; it < 8; it++) {
                int idx = t + it * 256;
                int row = idx >> 4, c16 = idx & 15;
                uint32_t doff = (uint32_t)((row * TSTRIDE + c16 * 8) * 2);
                cp16(bb + doff, bh + row * 128 + c16 * 8, 16u);
                cp16(bb + 34816 + doff, bl + row * 128 + c16 * 8, 16u);
            }
            CP_COMMIT();
            CP_WAIT1();
        } else {
            CP_WAIT0();
        }
        __syncthreads();

        float acc[2][8][4];
        #pragma unroll
        for (int i = 0; i < 2; i++)
            #pragma unroll
            for (int j = 0; j < 8; j++)
                #pragma unroll
                for (int c = 0; c < 4; c++) acc[i][j][c] = 0.f;

        uint32_t bbase = base + N2_B(itw & 1);
        #pragma unroll
        for (int ks = 0; ks < 8; ks++) {
            int kk = ks * 16;
            uint32_t aoff = (uint32_t)((aRow * TSTRIDE + kk + aK0) * 2);
            uint32_t a_hi[2][4], a_lo[2][4];
            ldsm4(base + N2_A_HI + aoff, a_hi[0]);
            ldsm4(base + N2_A_HI + aoff + 16 * TSTRIDE * 2, a_hi[1]);
            ldsm4(base + N2_A_LO + aoff, a_lo[0]);
            ldsm4(base + N2_A_LO + aoff + 16 * TSTRIDE * 2, a_lo[1]);

            uint32_t bhi[8][2], blo[8][2];
            #pragma unroll
            for (int nf2 = 0; nf2 < 4; nf2++) {
                uint32_t boff = (uint32_t)(((bRow + nf2 * 16) * TSTRIDE + kk + bK0) * 2);
                uint32_t r[4];
                ldsm4(bbase + boff, r);
                bhi[2 * nf2][0] = r[0]; bhi[2 * nf2][1] = r[1];
                bhi[2 * nf2 + 1][0] = r[2]; bhi[2 * nf2 + 1][1] = r[3];
                ldsm4(bbase + 34816 + boff, r);
                blo[2 * nf2][0] = r[0]; blo[2 * nf2][1] = r[1];
                blo[2 * nf2 + 1][0] = r[2]; blo[2 * nf2 + 1][1] = r[3];
            }
            #pragma unroll
            for (int nf = 0; nf < 8; nf++) {
                mma16816(acc[0][nf], a_hi[0], bhi[nf]);
                mma16816(acc[1][nf], a_hi[1], bhi[nf]);
                mma16816(acc[0][nf], a_hi[0], blo[nf]);
                mma16816(acc[1][nf], a_hi[1], blo[nf]);
                mma16816(acc[0][nf], a_lo[0], bhi[nf]);
                mma16816(acc[1][nf], a_lo[1], bhi[nf]);
            }
        }
        __syncthreads();   // before next iter's cp.async overwrites this buffer

        // epilogue for (w, half)
        int w = itw >> 1, half = itw & 1;
        float* out = (w == 0) ? oq : (w == 1) ? ok : (w == 2) ? ov : og;
        const float* bias = ((w == 0) ? bq : (w == 1) ? bk : (w == 2) ? bv : bs)
                            + half * 128;
        int r0 = bm + wm + (lane >> 2);
        int cB = wn + (lane & 3) * 2;
        #pragma unroll
        for (int mf = 0; mf < 2; mf++) {
            #pragma unroll
            for (int hl = 0; hl < 2; hl++) {
                int node = r0 + mf * 16 + hl * 8;
                if (node < NN) {
                    float* op = out + (size_t)node * HDD + half * 128;
                    #pragma unroll
                    for (int nf = 0; nf < 8; nf++) {
                        int col = cB + nf * 8;
                        float2 v;
                        v.x = acc[mf][nf][hl * 2 + 0] + bias[col];
                        v.y = acc[mf][nf][hl * 2 + 1] + bias[col + 1];
                        *(float2*)(op + col) = v;
                    }
                }
            }
        }
    }
}

// ---------------------------------------------------------------------------
// gemm_pq: M=64 body (unchanged from R15), grid.y = half
// ---------------------------------------------------------------------------
#define ATILE_B (64 * TSTRIDE * 2)
#define BTILE_B (128 * TSTRIDE * 2)
#define GEMM_SMEM (2 * ATILE_B + 2 * BTILE_B)
#define TA_HI 0
#define TA_LO ATILE_B
#define TB_HI (2 * ATILE_B)
#define TB_LO (2 * ATILE_B + BTILE_B)

__device__ __forceinline__ void gemm_body(
    __nv_bfloat16* smem,
    const __nv_bfloat16* Ahi, const __nv_bfloat16* Alo,
    const __nv_bfloat16* Bhi, const __nv_bfloat16* Blo,
    const float* bias, float* out, int Ktot, int outCol0)
{
    int t = threadIdx.x, lane = t & 31, wid = t >> 5;
    int bm = blockIdx.x * 64;
    int wm = (wid & 1) * 32;
    int wn = (wid >> 1) * 32;
    uint32_t base = smem_u32(smem);

    float acc[2][4][4];
    #pragma unroll
    for (int i = 0; i < 2; i++)
        #pragma unroll
        for (int j = 0; j < 4; j++)
            #pragma unroll
            for (int c = 0; c < 4; c++) acc[i][j][c] = 0.f;

    int aRow = wm + ((lane >> 3) & 1) * 8 + (lane & 7);
    int aK0 = (lane >> 4) * 8;
    int bRow = wn + (lane >> 4) * 8 + (lane & 7);
    int bK0 = ((lane >> 3) & 1) * 8;

    int nch = Ktot >> 7;
    for (int ch = 0; ch < nch; ch++) {
        if (ch) __syncthreads();
        #pragma unroll
        for (int it = 0; it < 4; it++) {
            int idx = t + it * 256;
            int row = idx >> 4, c16 = idx & 15;
            int grow = bm + row;
            uint32_t nb = grow < NN ? 16u : 0u;
            uint32_t doff = (uint32_t)((row * TSTRIDE + c16 * 8) * 2);
            cp16(base + TA_HI + doff, Ahi + (size_t)grow * Ktot + ch * 128 + c16 * 8, nb);
            cp16(base + TA_LO + doff, Alo + (size_t)grow * Ktot + ch * 128 + c16 * 8, nb);
        }
        #pragma unroll
        for (int it = 0; it < 8; it++) {
            int idx = t + it * 256;
            int row = idx >> 4, c16 = idx & 15;
            uint32_t doff = (uint32_t)((row * TSTRIDE + c16 * 8) * 2);
            cp16(base + TB_HI + doff, Bhi + (size_t)row * Ktot + ch * 128 + c16 * 8, 16u);
            cp16(base + TB_LO + doff, Blo + (size_t)row * Ktot + ch * 128 + c16 * 8, 16u);
        }
        CP_COMMIT();
        CP_WAIT0();
        __syncthreads();

        #pragma unroll
        for (int ks = 0; ks < 8; ks++) {
            int kk = ks * 16;
            uint32_t aoff = (uint32_t)((aRow * TSTRIDE + kk + aK0) * 2);
            uint32_t a_hi[2][4], a_lo[2][4];
            ldsm4(base + TA_HI + aoff, a_hi[0]);
            ldsm4(base + TA_HI + aoff + 16 * TSTRIDE * 2, a_hi[1]);
            ldsm4(base + TA_LO + aoff, a_lo[0]);
            ldsm4(base + TA_LO + aoff + 16 * TSTRIDE * 2, a_lo[1]);

            uint32_t bhi[4][2], blo[4][2];
            #pragma unroll
            for (int nf2 = 0; nf2 < 2; nf2++) {
                uint32_t boff = (uint32_t)(((bRow + nf2 * 16) * TSTRIDE + kk + bK0) * 2);
                uint32_t r[4];
                ldsm4(base + TB_HI + boff, r);
                bhi[2 * nf2][0] = r[0]; bhi[2 * nf2][1] = r[1];
                bhi[2 * nf2 + 1][0] = r[2]; bhi[2 * nf2 + 1][1] = r[3];
                ldsm4(base + TB_LO + boff, r);
                blo[2 * nf2][0] = r[0]; blo[2 * nf2][1] = r[1];
                blo[2 * nf2 + 1][0] = r[2]; blo[2 * nf2 + 1][1] = r[3];
            }
            #pragma unroll
            for (int nf = 0; nf < 4; nf++) {
                mma16816(acc[0][nf], a_hi[0], bhi[nf]);
                mma16816(acc[1][nf], a_hi[1], bhi[nf]);
                mma16816(acc[0][nf], a_hi[0], blo[nf]);
                mma16816(acc[1][nf], a_hi[1], blo[nf]);
                mma16816(acc[0][nf], a_lo[0], bhi[nf]);
                mma16816(acc[1][nf], a_lo[1], bhi[nf]);
            }
        }
    }

    int r0 = bm + wm + (lane >> 2);
    int cB = wn + (lane & 3) * 2;
    #pragma unroll
    for (int mf = 0; mf < 2; mf++) {
        #pragma unroll
        for (int hl = 0; hl < 2; hl++) {
            int node = r0 + mf * 16 + hl * 8;
            if (node < NN) {
                float* op = out + (size_t)node * HDD + outCol0;
                #pragma unroll
                for (int nf = 0; nf < 4; nf++) {
                    int col = cB + nf * 8;
                    float2 v;
                    v.x = acc[mf][nf][hl * 2 + 0];
                    v.y = acc[mf][nf][hl * 2 + 1];
                    if (bias) { v.x += bias[col]; v.y += bias[col + 1]; }
                    *(float2*)(op + col) = v;
                }
            }
        }
    }
}

__global__ void __launch_bounds__(256) gemm_pq(
    const __nv_bfloat16* __restrict__ ohi, const __nv_bfloat16* __restrict__ olo,
    const __nv_bfloat16* __restrict__ wthi, const __nv_bfloat16* __restrict__ wtlo,
    const float* __restrict__ b1, float* __restrict__ opq)
{
    extern __shared__ __nv_bfloat16 smem[];
    int half = blockIdx.y;
    gemm_body(smem, ohi, olo,
              wthi + WT_PQ_OFS + half * 128 * 256,
              wtlo + WT_PQ_OFS + half * 128 * 256,
              half == 0 ? b1 : (const float*)nullptr, opq, HDD, half * 128);
}

// ---------------------------------------------------------------------------
// Fused attention + bf16 split epilogue, 2-edge unrolled, direct src ids.
// ---------------------------------------------------------------------------
__global__ void __launch_bounds__(256) attn_kernel() {
    int w = (blockIdx.x * 256 + threadIdx.x) >> 5;
    if (w >= NN) return;
    int lane = threadIdx.x & 31;

    int beg = g_off[w], end = g_off[w + 1];

    float vacc[8] = {0.f, 0.f, 0.f, 0.f, 0.f, 0.f, 0.f, 0.f};
    float den = 0.f;

    if (beg != end) {
        const float* qp = g_q + (size_t)w * HDD + lane * 8;
        float4 q0 = *(const float4*)qp, q1 = *(const float4*)(qp + 4);
        int e = beg;
        for (; e + 1 < end; e += 2) {
            int s0 = g_eid[e], s1 = g_eid[e + 1];
            const float* kp0 = g_k + (size_t)s0 * HDD + lane * 8;
            const float* kp1 = g_k + (size_t)s1 * HDD + lane * 8;
            float4 ka0 = *(const float4*)kp0, kb0 = *(const float4*)(kp0 + 4);
            float4 ka1 = *(const float4*)kp1, kb1 = *(const float4*)(kp1 + 4);
            float d0 = q0.x * ka0.x + q0.y * ka0.y + q0.z * ka0.z + q0.w * ka0.w
                     + q1.x * kb0.x + q1.y * kb0.y + q1.z * kb0.z + q1.w * kb0.w;
            float d1 = q0.x * ka1.x + q0.y * ka1.y + q0.z * ka1.z + q0.w * ka1.w
                     + q1.x * kb1.x + q1.y * kb1.y + q1.z * kb1.z + q1.w * kb1.w;
            d0 += __shfl_xor_sync(0xffffffffu, d0, 4);
            d1 += __shfl_xor_sync(0xffffffffu, d1, 4);
            d0 += __shfl_xor_sync(0xffffffffu, d0, 2);
            d1 += __shfl_xor_sync(0xffffffffu, d1, 2);
            d0 += __shfl_xor_sync(0xffffffffu, d0, 1);
            d1 += __shfl_xor_sync(0xffffffffu, d1, 1);
            float ex0 = __expf(d0 * 0.125f);
            float ex1 = __expf(d1 * 0.125f);
            den += ex0 + ex1;
            const float* vp0 = g_v + (size_t)s0 * HDD + lane * 8;
            const float* vp1 = g_v + (size_t)s1 * HDD + lane * 8;
            float4 va0 = *(const float4*)vp0, vb0 = *(const float4*)(vp0 + 4);
            float4 va1 = *(const float4*)vp1, vb1 = *(const float4*)(vp1 + 4);
            vacc[0] += ex0 * va0.x + ex1 * va1.x;
            vacc[1] += ex0 * va0.y + ex1 * va1.y;
            vacc[2] += ex0 * va0.z + ex1 * va1.z;
            vacc[3] += ex0 * va0.w + ex1 * va1.w;
            vacc[4] += ex0 * vb0.x + ex1 * vb1.x;
            vacc[5] += ex0 * vb0.y + ex1 * vb1.y;
            vacc[6] += ex0 * vb0.z + ex1 * vb1.z;
            vacc[7] += ex0 * vb0.w + ex1 * vb1.w;
        }
        if (e < end) {
            int s = g_eid[e];
            const float* kp = g_k + (size_t)s * HDD + lane * 8;
            float4 k0 = *(const float4*)kp, k1 = *(const float4*)(kp + 4);
            float d = q0.x * k0.x + q0.y * k0.y + q0.z * k0.z + q0.w * k0.w
                    + q1.x * k1.x + q1.y * k1.y + q1.z * k1.z + q1.w * k1.w;
            d += __shfl_xor_sync(0xffffffffu, d, 4);
            d += __shfl_xor_sync(0xffffffffu, d, 2);
            d += __shfl_xor_sync(0xffffffffu, d, 1);
            float ex = __expf(d * 0.125f);
            den += ex;
            const float* vp = g_v + (size_t)s * HDD + lane * 8;
            float4 v0 = *(const float4*)vp, v1 = *(const float4*)(vp + 4);
            vacc[0] += ex * v0.x; vacc[1] += ex * v0.y;
            vacc[2] += ex * v0.z; vacc[3] += ex * v0.w;
            vacc[4] += ex * v1.x; vacc[5] += ex * v1.y;
            vacc[6] += ex * v1.z; vacc[7] += ex * v1.w;
        }
    }
    float inv = (beg != end) ? 1.f / (den + 1e-16f) : 0.f;
    const float* op = g_o + (size_t)w * HDD + lane * 8;
    float4 o0 = *(const float4*)op, o1 = *(const float4*)(op + 4);
    float fin[8] = {o0.x + vacc[0] * inv, o0.y + vacc[1] * inv,
                    o0.z + vacc[2] * inv, o0.w + vacc[3] * inv,
                    o1.x + vacc[4] * inv, o1.y + vacc[5] * inv,
                    o1.z + vacc[6] * inv, o1.w + vacc[7] * inv};
    __nv_bfloat16 h[8], l[8];
    #pragma unroll
    for (int c = 0; c < 8; c++) split_bf(fin[c], h[c], l[c]);
    *(uint4*)(g_ohi + (size_t)w * HDD + lane * 8) = *(uint4*)h;
    *(uint4*)(g_olo + (size_t)w * HDD + lane * 8) = *(uint4*)l;
}

// ---------------------------------------------------------------------------
// Edge MLP (tensorized stage 2) — unchanged from R15
// ---------------------------------------------------------------------------
#define ME_H1L  34816
#define ME_W2H  69632
#define ME_W2L  87040
#define ME_SMEM_BYTES 104448

__global__ void __launch_bounds__(256) mlp_edge(
    const float* __restrict__ b2, const float* __restrict__ W3,
    const float* __restrict__ b3, float* __restrict__ outp)
{
    extern __shared__ __nv_bfloat16 sm[];
    __nv_bfloat16* H1h = sm;
    __nv_bfloat16* H1l = sm + ME_H1L / 2;
    __nv_bfloat16* W2h = sm + ME_W2H / 2;
    __nv_bfloat16* W2l = sm + ME_W2L / 2;

    __shared__ int   sidx[128], didx[128];
    __shared__ float b2s[64], W3s[64];
    __shared__ float part[128][2];
    __shared__ float b3s;

    int t = threadIdx.x, lane = t & 31, wid = t >> 5;
    int e0 = blockIdx.x * 128;
    uint32_t base = smem_u32(sm);

    if (t < 128) { sidx[t] = g_src[e0 + t]; didx[t] = g_dst[e0 + t]; }
    if (t < 64)  { b2s[t] = b2[t]; W3s[t] = W3[t]; }
    if (t == 0)  { b3s = b3[0]; }
    #pragma unroll
    for (int it = 0; it < 4; it++) {
        int idx = t + it * 256;
        int row = idx >> 4, c8 = idx & 15;
        *(uint4*)(W2h + row * TSTRIDE + c8 * 8) = *(const uint4*)(g_w2h + row * 128 + c8 * 8);
        *(uint4*)(W2l + row * TSTRIDE + c8 * 8) = *(const uint4*)(g_w2l + row * 128 + c8 * 8);
    }
    __syncthreads();

    {
        int r = t >> 1, hh = t & 1;
        const float* pp = g_PQ + (size_t)sidx[r] * HDD + hh * 64;
        const float* qq = g_PQ + (size_t)didx[r] * HDD + 128 + hh * 64;
        #pragma unroll
        for (int j = 0; j < 16; j++) {
            float4 a = *(const float4*)(pp + j * 4);
            float4 b = *(const float4*)(qq + j * 4);
            float v[4] = {fmaxf(a.x + b.x, 0.f), fmaxf(a.y + b.y, 0.f),
                          fmaxf(a.z + b.z, 0.f), fmaxf(a.w + b.w, 0.f)};
            __nv_bfloat16 h[4], l[4];
            #pragma unroll
            for (int c = 0; c < 4; c++) split_bf(v[c], h[c], l[c]);
            *(uint2*)(H1h + r * TSTRIDE + hh * 64 + j * 4) = *(uint2*)h;
            *(uint2*)(H1l + r * TSTRIDE + hh * 64 + j * 4) = *(uint2*)l;
        }
    }
    __syncthreads();

    int wm = (wid & 3) * 32;
    int wn = (wid >> 2) * 32;

    float acc[2][4][4];
    #pragma unroll
    for (int i = 0; i < 2; i++)
        #pragma unroll
        for (int j = 0; j < 4; j++)
            #pragma unroll
            for (int c = 0; c < 4; c++) acc[i][j][c] = 0.f;

    int aRow = wm + ((lane >> 3) & 1) * 8 + (lane & 7);
    int aK0 = (lane >> 4) * 8;
    int bRow = wn + (lane >> 4) * 8 + (lane & 7);
    int bK0 = ((lane >> 3) & 1) * 8;

    #pragma unroll
    for (int ks = 0; ks < 8; ks++) {
        int kk = ks * 16;
        uint32_t aoff = (uint32_t)((aRow * TSTRIDE + kk + aK0) * 2);
        uint32_t a_hi[2][4], a_lo[2][4];
        ldsm4(base + aoff, a_hi[0]);
        ldsm4(base + aoff + 16 * TSTRIDE * 2, a_hi[1]);
        ldsm4(base + ME_H1L + aoff, a_lo[0]);
        ldsm4(base + ME_H1L + aoff + 16 * TSTRIDE * 2, a_lo[1]);

        uint32_t bhi[4][2], blo[4][2];
        #pragma unroll
        for (int nf2 = 0; nf2 < 2; nf2++) {
            uint32_t boff = (uint32_t)(((bRow + nf2 * 16) * TSTRIDE + kk + bK0) * 2);
            uint32_t r[4];
            ldsm4(base + ME_W2H + boff, r);
            bhi[2 * nf2][0] = r[0]; bhi[2 * nf2][1] = r[1];
            bhi[2 * nf2 + 1][0] = r[2]; bhi[2 * nf2 + 1][1] = r[3];
            ldsm4(base + ME_W2L + boff, r);
            blo[2 * nf2][0] = r[0]; blo[2 * nf2][1] = r[1];
            blo[2 * nf2 + 1][0] = r[2]; blo[2 * nf2 + 1][1] = r[3];
        }
        #pragma unroll
        for (int nf = 0; nf < 4; nf++) {
            mma16816(acc[0][nf], a_hi[0], bhi[nf]);
            mma16816(acc[1][nf], a_hi[1], bhi[nf]);
            mma16816(acc[0][nf], a_hi[0], blo[nf]);
            mma16816(acc[1][nf], a_hi[1], blo[nf]);
            mma16816(acc[0][nf], a_lo[0], bhi[nf]);
            mma16816(acc[1][nf], a_lo[1], bhi[nf]);
        }
    }

    #pragma unroll
    for (int mf = 0; mf < 2; mf++) {
        #pragma unroll
        for (int rh = 0; rh < 2; rh++) {
            float s = 0.f;
            #pragma unroll
            for (int nf = 0; nf < 4; nf++) {
                int col = wn + nf * 8 + (lane & 3) * 2;
                float v0 = fmaxf(acc[mf][nf][rh * 2 + 0] + b2s[col], 0.f);
                float v1 = fmaxf(acc[mf][nf][rh * 2 + 1] + b2s[col + 1], 0.f);
                s += v0 * W3s[col] + v1 * W3s[col + 1];
            }
            s += __shfl_xor_sync(0xffffffffu, s, 1);
            s += __shfl_xor_sync(0xffffffffu, s, 2);
            if ((lane & 3) == 0)
                part[wm + mf * 16 + rh * 8 + (lane >> 2)][wid >> 2] = s;
        }
    }
    __syncthreads();
    if (t < 128) {
        float s = part[t][0] + part[t][1] + b3s;
        float rv = 1.f / (1.f + expf(-s));
        outp[e0 + t] = rv * 4.f + 1.f;
    }
}

// ---------------------------------------------------------------------------
extern "C" void kernel_launch(void* const* d_in, const int* in_sizes, int n_in,
                              void* d_out, int out_size)
{
    const int* ei     = (const int*)d_in[0];
    const float* x    = (const float*)d_in[2];
    const float* mem  = (const float*)d_in[3];
    const float* Wq   = (const float*)d_in[4];
    const float* bq   = (const float*)d_in[5];
    const float* Wk   = (const float*)d_in[6];
    const float* bk   = (const float*)d_in[7];
    const float* Wv   = (const float*)d_in[8];
    const float* bv   = (const float*)d_in[9];
    const float* Ws   = (const float*)d_in[10];
    const float* bs   = (const float*)d_in[11];
    const float* W1   = (const float*)d_in[12];
    const float* b1   = (const float*)d_in[13];
    const float* W2   = (const float*)d_in[14];
    const float* b2   = (const float*)d_in[15];
    const float* W3   = (const float*)d_in[16];
    const float* b3   = (const float*)d_in[17];
    float* outp = (float*)d_out;

    cudaFuncSetAttribute(mlp_edge, cudaFuncAttributeMaxDynamicSharedMemorySize,
                         ME_SMEM_BYTES);
    cudaFuncSetAttribute(gemm_node2, cudaFuncAttributeMaxDynamicSharedMemorySize,
                         N2_SMEM);
    cudaFuncSetAttribute(gemm_pq, cudaFuncAttributeMaxDynamicSharedMemorySize,
                         GEMM_SMEM);

    // CSR build + operand conversion
    zero_cnt<<<(NN + 255) / 256, 256>>>();
    prep_kernel<<<(NE + 255) / 256, 256>>>(ei);
    scan_kernel<<<1, SCAN_T>>>();
    scatter_kernel<<<(NE + 255) / 256, 256>>>();
    conv_h<<<(NN * HIDN / 4 + 255) / 256, 256>>>(x, mem);
    conv_w<<<(CW_TOT + 255) / 256, 256>>>(Wq, Wk, Wv, Ws, W1, W2);

    // device pointers for __device__ globals
    __nv_bfloat16 *ahi, *alo, *ohi, *olo, *wthi, *wtlo;
    float *dq, *dk, *dv, *dg, *dpq;
    cudaGetSymbolAddress((void**)&ahi, g_ahi);
    cudaGetSymbolAddress((void**)&alo, g_alo);
    cudaGetSymbolAddress((void**)&ohi, g_ohi);
    cudaGetSymbolAddress((void**)&olo, g_olo);
    cudaGetSymbolAddress((void**)&wthi, g_wthi);
    cudaGetSymbolAddress((void**)&wtlo, g_wtlo);
    cudaGetSymbolAddress((void**)&dq, g_q);
    cudaGetSymbolAddress((void**)&dk, g_k);
    cudaGetSymbolAddress((void**)&dv, g_v);
    cudaGetSymbolAddress((void**)&dg, g_o);
    cudaGetSymbolAddress((void**)&dpq, g_PQ);

    int gxn = (NN + 127) / 128;
    gemm_node2<<<gxn, 256, N2_SMEM>>>(ahi, alo, wthi, wtlo,
                                      bq, bk, bv, bs, dq, dk, dv, dg);

    attn_kernel<<<(NN * 32 + 255) / 256, 256>>>();

    int gx = (NN + 63) / 64;
    dim3 gp(gx, 2);
    gemm_pq<<<gp, 256, GEMM_SMEM>>>(ohi, olo, wthi, wtlo, b1, dpq);

    mlp_edge<<<NE / 128, 256, ME_SMEM_BYTES>>>(b2, W3, b3, outp);
}